// round 14
// baseline (speedup 1.0000x reference)
#include <cuda_runtime.h>
#include <cuda_fp16.h>
#include <math.h>
#include <stdint.h>

#define S_LEN   2048
#define NBATCH  2
#define EMB     2048
#define NHEADS  16
#define NKV     4
#define HD      128
#define KVW     1024   // 2*NKV*HD

// ---------------- scratch (device globals: no allocation allowed) ----------------
__device__ float  g_cs[S_LEN * 64];   // cos table [s][d]
__device__ float  g_sn[S_LEN * 64];   // sin table [s][d]
// fp16 operand buffers
__device__ __half g_xs [(size_t)NBATCH * S_LEN * EMB];     // x
__device__ __half g_wq [(size_t)EMB * EMB];
__device__ __half g_wkv[(size_t)KVW * EMB];
__device__ __half g_wo [(size_t)EMB * EMB];
__device__ __half g_qs [(size_t)NBATCH * S_LEN * EMB];     // rope Q (scale folded)
__device__ __half g_ks [(size_t)NBATCH * S_LEN * NKV * HD];
__device__ __half g_vs [(size_t)NBATCH * S_LEN * NKV * HD];
__device__ __half g_as [(size_t)NBATCH * S_LEN * EMB];     // attention out

// ---------------- fast exp --------------------------------------------------------
__device__ __forceinline__ float fast_exp(float x) {
    float y  = fmaxf(x * 1.4426950408889634f, -127.0f);
    float fl = floorf(y);
    float f  = y - fl;
    float p  = 1.5403530e-4f;
    p = fmaf(p, f, 1.3333558e-3f);
    p = fmaf(p, f, 9.6181291e-3f);
    p = fmaf(p, f, 5.5504109e-2f);
    p = fmaf(p, f, 2.4022651e-1f);
    p = fmaf(p, f, 6.9314718e-1f);
    p = fmaf(p, f, 1.0f);
    int e = (int)fl;
    float s = __int_as_float((e + 127) << 23);
    return p * s;
}

// ---------------- mma.sync / ldmatrix / cp.async helpers --------------------------
__device__ __forceinline__ uint32_t smem_u32(const void* p) {
    uint32_t a;
    asm("{ .reg .u64 t; cvta.to.shared.u64 t, %1; cvt.u32.u64 %0, t; }" : "=r"(a) : "l"(p));
    return a;
}
#define LDSM_X4(r0, r1, r2, r3, addr) \
    asm volatile("ldmatrix.sync.aligned.m8n8.x4.shared.b16 {%0,%1,%2,%3}, [%4];" \
        : "=r"(r0), "=r"(r1), "=r"(r2), "=r"(r3) : "r"(addr))
#define LDSM_T_X4(r0, r1, r2, r3, addr) \
    asm volatile("ldmatrix.sync.aligned.m8n8.x4.trans.shared.b16 {%0,%1,%2,%3}, [%4];" \
        : "=r"(r0), "=r"(r1), "=r"(r2), "=r"(r3) : "r"(addr))
#define MMAH(c0, c1, c2, c3, a0, a1, a2, a3, b0, b1) \
    asm volatile("mma.sync.aligned.m16n8k16.row.col.f32.f16.f16.f32 " \
        "{%0,%1,%2,%3}, {%4,%5,%6,%7}, {%8,%9}, {%0,%1,%2,%3};" \
        : "+f"(c0), "+f"(c1), "+f"(c2), "+f"(c3) \
        : "r"(a0), "r"(a1), "r"(a2), "r"(a3), "r"(b0), "r"(b1))
#define CP16(d, s) \
    asm volatile("cp.async.cg.shared.global [%0], [%1], 16;" :: "r"(d), "l"(s))
#define CP_COMMIT asm volatile("cp.async.commit_group;" ::: "memory")
#define CP_WAIT2  asm volatile("cp.async.wait_group 2;" ::: "memory")
#define CP_WAIT1  asm volatile("cp.async.wait_group 1;" ::: "memory")
#define CP_WAIT0  asm volatile("cp.async.wait_group 0;" ::: "memory")

// ================= merged prep: splits + rope tables (one launch) =================
#define NX4   (NBATCH * S_LEN * EMB / 4)
#define NWQ4  (EMB * EMB / 4)
#define NWKV4 (KVW * EMB / 4)
#define NTAB  (S_LEN * 64)
#define PREP_TOTAL (NX4 + NWQ4 + NWKV4 + NWQ4 + NTAB)

__global__ void prep_kernel(const float* __restrict__ x,  const float* __restrict__ Wq,
                            const float* __restrict__ Wkv, const float* __restrict__ Wo)
{
    int i = blockIdx.x * blockDim.x + threadIdx.x;
    const float* src;
    __half* dst;
    if (i < NX4)                      { src = x;   dst = g_xs; }
    else if ((i -= NX4) < NWQ4)       { src = Wq;  dst = g_wq; }
    else if ((i -= NWQ4) < NWKV4)     { src = Wkv; dst = g_wkv; }
    else if ((i -= NWKV4) < NWQ4)     { src = Wo;  dst = g_wo; }
    else {
        i -= NWQ4;
        if (i >= NTAB) return;
        int s = i >> 6, d = i & 63;
        double invf = pow(10000.0, -(double)d / 64.0);
        double ang = (double)s * invf;
        double k = floor(ang * 0.15915494309189535);
        float a = (float)(ang - k * 6.283185307179586);
        g_cs[i] = cosf(a);
        g_sn[i] = sinf(a);
        return;
    }
    float4 v = ((const float4*)src)[i];
    __half2 h01 = __floats2half2_rn(v.x, v.y);
    __half2 h23 = __floats2half2_rn(v.z, v.w);
    uint2 hv; hv.x = *(uint32_t*)&h01; hv.y = *(uint32_t*)&h23;
    ((uint2*)dst)[i] = hv;
}

// ========= GEMM mainloop: K-chunk 32, 4-stage ring, ONE sync per chunk ============
#define GS_ROW    40                       // padded row: 40 halfs = 80 B
#define GS_TILE   (128 * GS_ROW * 2)       // 10240 B
#define GS_STAGE  (2 * GS_TILE)            // 20480 B (A, W)
#define GEMM_SMEM (4 * GS_STAGE)           // 81920 B
#define QKV_SMEM  GEMM_SMEM                // epilogue fp32 tile 67584 B fits

#define LOAD_STAGE(c, bufi) do {                                                       \
    int _k0 = (c) << 5;                                                                \
    uint32_t _st = sbase + (uint32_t)((bufi) * GS_STAGE);                              \
    _Pragma("unroll")                                                                  \
    for (int _i = 0; _i < 2; _i++) {                                                   \
        int _ch = tid + _i * 256;                                                      \
        int _r = _ch >> 2, _cl = _ch & 3;                                              \
        uint32_t _d = _st + (uint32_t)(_r * (GS_ROW * 2) + _cl * 16);                  \
        CP16(_d,           A_gp + (size_t)(m0 + _r) * Kd + _k0 + _cl * 8);             \
        CP16(_d + GS_TILE, W_gp + (size_t)(n0 + _r) * Kd + _k0 + _cl * 8);             \
    } } while (0)

#define GEMM_MAINLOOP(K)                                                               \
    const int rIT  = lane & 7;                                                         \
    const int b0_  = (lane >> 3) & 1;                                                  \
    const int b1_  = (lane >> 4) & 1;                                                  \
    const uint32_t aLane = (uint32_t)(((b0_ * 8 + rIT) * GS_ROW + b1_ * 8) * 2);       \
    const uint32_t bLane = (uint32_t)(((b1_ * 8 + rIT) * GS_ROW + b0_ * 8) * 2);       \
    const int nch = (K) >> 5;                                                          \
    LOAD_STAGE(0, 0); CP_COMMIT;                                                       \
    LOAD_STAGE(1, 1); CP_COMMIT;                                                       \
    LOAD_STAGE(2, 2); CP_COMMIT;                                                       \
    for (int c = 0; c < nch; c++) {                                                    \
        int rem = nch - c;                                                             \
        if (rem >= 3) CP_WAIT2; else if (rem == 2) CP_WAIT1; else CP_WAIT0;            \
        __syncthreads();                                                               \
        if (c + 3 < nch) { LOAD_STAGE(c + 3, (c + 3) & 3); CP_COMMIT; }                \
        const uint32_t bb = sbase + (uint32_t)((c & 3) * GS_STAGE);                    \
        const uint32_t Ahs = bb;                                                       \
        const uint32_t Whs = bb + GS_TILE;                                             \
        _Pragma("unroll")                                                              \
        for (int ks = 0; ks < 2; ks++) {                                               \
            const uint32_t kOff = (uint32_t)(ks * 32);                                 \
            uint32_t ah[4][4], bh[4][2];                                               \
            _Pragma("unroll")                                                          \
            for (int mf = 0; mf < 4; mf++) {                                           \
                uint32_t addr = Ahs + (uint32_t)((wm + mf * 16) * GS_ROW * 2) + kOff + aLane; \
                LDSM_X4(ah[mf][0], ah[mf][1], ah[mf][2], ah[mf][3], addr);             \
            }                                                                          \
            _Pragma("unroll")                                                          \
            for (int np = 0; np < 2; np++) {                                           \
                uint32_t addr = Whs + (uint32_t)((wn + np * 16) * GS_ROW * 2) + kOff + bLane; \
                uint32_t r0, r1, r2, r3;                                               \
                LDSM_X4(r0, r1, r2, r3, addr);                                         \
                bh[np * 2][0] = r0; bh[np * 2][1] = r1;                                \
                bh[np * 2 + 1][0] = r2; bh[np * 2 + 1][1] = r3;                        \
            }                                                                          \
            _Pragma("unroll")                                                          \
            for (int mf = 0; mf < 4; mf++)                                             \
                _Pragma("unroll")                                                      \
                for (int nf = 0; nf < 4; nf++)                                         \
                    MMAH(acc[mf][nf][0], acc[mf][nf][1], acc[mf][nf][2], acc[mf][nf][3], \
                         ah[mf][0], ah[mf][1], ah[mf][2], ah[mf][3],                   \
                         bh[nf][0], bh[nf][1]);                                        \
        }                                                                              \
    }

// ================= fused QKV projection + RoPE/convert ============================
__global__ __launch_bounds__(256, 2)
void gemm_qkv(const __half* __restrict__ xs_g,
              const __half* __restrict__ wq_g, const __half* __restrict__ wkv_g,
              const float* __restrict__ bq_g, const float* __restrict__ bkv_g)
{
    extern __shared__ char smp[];
    const uint32_t sbase = smem_u32(smp);

    const int tid  = threadIdx.x;
    const int wid  = tid >> 5;
    const int lane = tid & 31;
    const int bx   = blockIdx.x;
    const bool isQ = bx < 16;
    const int m0   = blockIdx.y * 128;
    const int n0   = isQ ? bx * 128 : (bx - 16) * 128;
    const int wm   = (wid >> 2) * 64;
    const int wn   = (wid & 3) * 32;
    const int Kd   = EMB;

    const __half* A_gp = xs_g;
    const __half* W_gp = isQ ? wq_g : wkv_g;
    const float*  bias = isQ ? bq_g : bkv_g;

    float acc[4][4][4];
    #pragma unroll
    for (int i = 0; i < 4; i++)
        #pragma unroll
        for (int j = 0; j < 4; j++)
            #pragma unroll
            for (int e = 0; e < 4; e++) acc[i][j][e] = 0.f;

    GEMM_MAINLOOP(EMB)

    const int trow  = lane >> 2;
    const int tcol2 = (lane & 3) * 2;
    #pragma unroll
    for (int nf = 0; nf < 4; nf++) {
        float2 bv = *(const float2*)&bias[n0 + wn + nf * 8 + tcol2];
        #pragma unroll
        for (int mf = 0; mf < 4; mf++) {
            acc[mf][nf][0] += bv.x; acc[mf][nf][1] += bv.y;
            acc[mf][nf][2] += bv.x; acc[mf][nf][3] += bv.y;
        }
    }

    if (!isQ && n0 >= 512) {
        // ---- V tile: direct fp16 convert ----
        #pragma unroll
        for (int mf = 0; mf < 4; mf++) {
            #pragma unroll
            for (int nf = 0; nf < 4; nf++) {
                int grow = m0 + wm + mf * 16 + trow;
                int vcol = n0 - 512 + wn + nf * 8 + tcol2;
                __half2 ha = __floats2half2_rn(acc[mf][nf][0], acc[mf][nf][1]);
                __half2 hb = __floats2half2_rn(acc[mf][nf][2], acc[mf][nf][3]);
                *(uint32_t*)&g_vs[(size_t)grow * 512 + vcol]       = *(uint32_t*)&ha;
                *(uint32_t*)&g_vs[(size_t)(grow + 8) * 512 + vcol] = *(uint32_t*)&hb;
            }
        }
        return;
    }

    // ---- Q or K tile: stage fp32 to smem, RoPE, store fp16 ----
    __syncthreads();
    float* smf = (float*)smp;           // [128][132]
    #pragma unroll
    for (int mf = 0; mf < 4; mf++) {
        #pragma unroll
        for (int nf = 0; nf < 4; nf++) {
            int r = wm + mf * 16 + trow;
            int cidx = wn + nf * 8 + tcol2;
            *(float2*)&smf[r * 132 + cidx]       = make_float2(acc[mf][nf][0], acc[mf][nf][1]);
            *(float2*)&smf[(r + 8) * 132 + cidx] = make_float2(acc[mf][nf][2], acc[mf][nf][3]);
        }
    }
    __syncthreads();

    const float sc = isQ ? 0.08838834764831845f : 1.0f;
    __half* dst    = isQ ? g_qs : g_ks;
    const int width = isQ ? EMB : 512;

    #pragma unroll
    for (int i = 0; i < 16; i++) {
        int idx = tid + i * 256;
        int row = idx >> 5;
        int dp  = (idx & 31) * 2;
        int grow = m0 + row;
        int s = grow & (S_LEN - 1);
        float t1a = smf[row * 132 + dp];
        float t1b = smf[row * 132 + dp + 1];
        float t2a = smf[row * 132 + dp + 64];
        float t2b = smf[row * 132 + dp + 65];
        float2 csv = *(const float2*)&g_cs[s * 64 + dp];
        float2 snv = *(const float2*)&g_sn[s * 64 + dp];
        float o1a = (t1a * csv.x - t2a * snv.x) * sc;
        float o1b = (t1b * csv.y - t2b * snv.y) * sc;
        float o2a = (t2a * csv.x + t1a * snv.x) * sc;
        float o2b = (t2b * csv.y + t1b * snv.y) * sc;
        __half2 h1 = __floats2half2_rn(o1a, o1b);
        __half2 h2 = __floats2half2_rn(o2a, o2b);
        size_t ob = (size_t)grow * width + n0 + dp;
        *(uint32_t*)&dst[ob]      = *(uint32_t*)&h1;
        *(uint32_t*)&dst[ob + 64] = *(uint32_t*)&h2;
    }
}

// ================= plain GEMM for O projection ====================================
__global__ __launch_bounds__(256, 2)
void gemm_fp16(const __half* __restrict__ A_gp, const __half* __restrict__ W_gp,
               float* __restrict__ C, int N, int K)
{
    extern __shared__ char smp[];
    const uint32_t sbase = smem_u32(smp);

    const int tid  = threadIdx.x;
    const int wid  = tid >> 5;
    const int lane = tid & 31;
    const int m0   = blockIdx.y * 128;
    const int n0   = blockIdx.x * 128;
    const int wm   = (wid >> 2) * 64;
    const int wn   = (wid & 3) * 32;
    const int Kd   = K;

    float acc[4][4][4];
    #pragma unroll
    for (int i = 0; i < 4; i++)
        #pragma unroll
        for (int j = 0; j < 4; j++)
            #pragma unroll
            for (int e = 0; e < 4; e++) acc[i][j][e] = 0.f;

    GEMM_MAINLOOP(K)

    const int trow  = lane >> 2;
    const int tcol2 = (lane & 3) * 2;
    #pragma unroll
    for (int mf = 0; mf < 4; mf++) {
        #pragma unroll
        for (int nf = 0; nf < 4; nf++) {
            int row = m0 + wm + mf * 16 + trow;
            int col = n0 + wn + nf * 8 + tcol2;
            *(float2*)&C[(size_t)row * N + col]       = make_float2(acc[mf][nf][0], acc[mf][nf][1]);
            *(float2*)&C[(size_t)(row + 8) * N + col] = make_float2(acc[mf][nf][2], acc[mf][nf][3]);
        }
    }
}

// ===== fp16 HMMA attention (FA2, 64 rows, Q in regs, 3-buffer KV, 1 sync/tile) ====
#define AP        272
#define KT_BYTES  (64 * AP)
#define KVBUF     (2 * KT_BYTES)                 // K, V
#define ATTN_SMEM (3 * KVBUF)                    // 104448

__global__ __launch_bounds__(128, 2) void attn_mma() {
    extern __shared__ char smb[];
    const uint32_t sb = smem_u32(smb);

    const int tid  = threadIdx.x;
    const int wid  = tid >> 5;          // 0..3
    const int lane = tid & 31;
    const int q0   = blockIdx.x * 64;
    const int h    = blockIdx.y;
    const int b    = blockIdx.z;
    const int kvh  = h >> 2;

    const int rIT  = lane & 7;
    const int b3   = (lane >> 3) & 1;
    const int b4   = (lane >> 4) & 1;
    const uint32_t offA = (uint32_t)((b3 * 8 + rIT) * AP + b4 * 16);
    const uint32_t offB = (uint32_t)((b4 * 8 + rIT) * AP + b3 * 16);

    const __half* q_g = g_qs + (size_t)(b * S_LEN + q0) * EMB + h * HD;
    const __half* k_g = g_ks + (size_t)b * S_LEN * 512 + kvh * HD;
    const __half* v_g = g_vs + (size_t)b * S_LEN * 512 + kvh * HD;

    // ---- stage Q through buf0, LDSM to registers (loop-invariant) ----
    #pragma unroll
    for (int i = 0; i < 8; i++) {
        int c = tid + i * 128;
        int row = c >> 4, col = c & 15;
        CP16(sb + (uint32_t)(row * AP + col * 16), q_g + (size_t)row * EMB + col * 8);
    }
    CP_COMMIT; CP_WAIT0;
    __syncthreads();
    uint32_t qfr[8][4];
    {
        const uint32_t qwarp = sb + (uint32_t)(wid * 16 * AP);
        #pragma unroll
        for (int ks = 0; ks < 8; ks++)
            LDSM_X4(qfr[ks][0], qfr[ks][1], qfr[ks][2], qfr[ks][3], qwarp + ks * 32 + offA);
    }
    __syncthreads();

    #define LOAD_KV(T, BUF) do {                                                       \
        size_t _j = (size_t)((T) * 64);                                                \
        uint32_t _dst = sb + (uint32_t)((BUF) * KVBUF);                                \
        _Pragma("unroll")                                                              \
        for (int _i = 0; _i < 8; _i++) {                                               \
            int _c = tid + _i * 128;                                                   \
            int _row = _c >> 4, _col = _c & 15;                                        \
            uint32_t _d0 = _dst + (uint32_t)(_row * AP + _col * 16);                   \
            size_t _s0 = (_j + _row) * 512 + _col * 8;                                 \
            CP16(_d0,            k_g + _s0);                                           \
            CP16(_d0 + KT_BYTES, v_g + _s0);                                           \
        } } while (0)

    LOAD_KV(0, 0); CP_COMMIT;
    LOAD_KV(1, 1); CP_COMMIT;

    float m0 = -1e30f, m1 = -1e30f, l0 = 0.f, l1 = 0.f;
    float ofr[16][4];
    #pragma unroll
    for (int i = 0; i < 16; i++)
        #pragma unroll
        for (int e = 0; e < 4; e++) ofr[i][e] = 0.f;

    int bt = 0;                     // t % 3
    for (int t = 0; t < 32; t++) {
        if (t + 2 <= 31) CP_WAIT1; else CP_WAIT0;
        __syncthreads();
        if (t + 2 < 32) {
            int nb = bt + 2; if (nb >= 3) nb -= 3;
            LOAD_KV(t + 2, nb); CP_COMMIT;
        }

        const uint32_t kvb = sb + (uint32_t)(bt * KVBUF);
        const uint32_t K_s = kvb;
        const uint32_t V_s = kvb + KT_BYTES;

        float sfr[8][4];
        #pragma unroll
        for (int i = 0; i < 8; i++)
            #pragma unroll
            for (int e = 0; e < 4; e++) sfr[i][e] = 0.f;

        #pragma unroll
        for (int ks = 0; ks < 8; ks++) {
            uint32_t bh[8][2];
            #pragma unroll
            for (int np = 0; np < 4; np++) {
                uint32_t r0, r1, r2, r3;
                LDSM_X4(r0, r1, r2, r3, K_s + (uint32_t)(np * 16 * AP) + ks * 32 + offB);
                bh[np * 2][0] = r0; bh[np * 2][1] = r1;
                bh[np * 2 + 1][0] = r2; bh[np * 2 + 1][1] = r3;
            }
            #pragma unroll
            for (int nf = 0; nf < 8; nf++)
                MMAH(sfr[nf][0], sfr[nf][1], sfr[nf][2], sfr[nf][3],
                     qfr[ks][0], qfr[ks][1], qfr[ks][2], qfr[ks][3],
                     bh[nf][0], bh[nf][1]);
        }

        float mx0 = -1e30f, mx1 = -1e30f;
        #pragma unroll
        for (int nf = 0; nf < 8; nf++) {
            mx0 = fmaxf(mx0, fmaxf(sfr[nf][0], sfr[nf][1]));
            mx1 = fmaxf(mx1, fmaxf(sfr[nf][2], sfr[nf][3]));
        }
        mx0 = fmaxf(mx0, __shfl_xor_sync(0xffffffffu, mx0, 1));
        mx0 = fmaxf(mx0, __shfl_xor_sync(0xffffffffu, mx0, 2));
        mx1 = fmaxf(mx1, __shfl_xor_sync(0xffffffffu, mx1, 1));
        mx1 = fmaxf(mx1, __shfl_xor_sync(0xffffffffu, mx1, 2));
        float mn0 = fmaxf(m0, mx0), mn1 = fmaxf(m1, mx1);
        float al0 = fast_exp(m0 - mn0), al1 = fast_exp(m1 - mn1);

        uint32_t ph[4][4];
        float rs0 = 0.f, rs1 = 0.f;
        #pragma unroll
        for (int nf = 0; nf < 8; nf++) {
            float p0 = fast_exp(sfr[nf][0] - mn0);
            float p1 = fast_exp(sfr[nf][1] - mn0);
            float p2 = fast_exp(sfr[nf][2] - mn1);
            float p3 = fast_exp(sfr[nf][3] - mn1);
            rs0 += p0 + p1; rs1 += p2 + p3;
            __half2 h01 = __floats2half2_rn(p0, p1);
            __half2 h23 = __floats2half2_rn(p2, p3);
            int kb = nf >> 1, hf = (nf & 1) * 2;
            ph[kb][hf]     = *(uint32_t*)&h01;
            ph[kb][hf + 1] = *(uint32_t*)&h23;
        }
        rs0 += __shfl_xor_sync(0xffffffffu, rs0, 1);
        rs0 += __shfl_xor_sync(0xffffffffu, rs0, 2);
        rs1 += __shfl_xor_sync(0xffffffffu, rs1, 1);
        rs1 += __shfl_xor_sync(0xffffffffu, rs1, 2);
        l0 = l0 * al0 + rs0;
        l1 = l1 * al1 + rs1;
        m0 = mn0; m1 = mn1;

        #pragma unroll
        for (int nf = 0; nf < 16; nf++) {
            ofr[nf][0] *= al0; ofr[nf][1] *= al0;
            ofr[nf][2] *= al1; ofr[nf][3] *= al1;
        }

        #pragma unroll
        for (int kb = 0; kb < 4; kb++) {
            #pragma unroll
            for (int db = 0; db < 8; db++) {
                uint32_t vh0, vh1, vh2, vh3;
                uint32_t va = (uint32_t)(kb * 16 * AP + db * 32) + offA;
                LDSM_T_X4(vh0, vh1, vh2, vh3, V_s + va);
                int nf = db * 2;
                MMAH(ofr[nf][0], ofr[nf][1], ofr[nf][2], ofr[nf][3],
                     ph[kb][0], ph[kb][1], ph[kb][2], ph[kb][3], vh0, vh1);
                MMAH(ofr[nf + 1][0], ofr[nf + 1][1], ofr[nf + 1][2], ofr[nf + 1][3],
                     ph[kb][0], ph[kb][1], ph[kb][2], ph[kb][3], vh2, vh3);
            }
        }

        if (++bt == 3) bt = 0;
    }

    float li0 = 1.0f / l0, li1 = 1.0f / l1;
    int row0 = q0 + wid * 16 + (lane >> 2);
    size_t ob = (size_t)(b * S_LEN + row0) * EMB + h * HD + (lane & 3) * 2;
    #pragma unroll
    for (int nf = 0; nf < 16; nf++) {
        __half2 h01 = __floats2half2_rn(ofr[nf][0] * li0, ofr[nf][1] * li0);
        __half2 h23 = __floats2half2_rn(ofr[nf][2] * li1, ofr[nf][3] * li1);
        *(uint32_t*)&g_as[ob + nf * 8]           = *(uint32_t*)&h01;
        *(uint32_t*)&g_as[ob + 8 * EMB + nf * 8] = *(uint32_t*)&h23;
    }
    #undef LOAD_KV
}

// ---------------- launch ----------------------------------------------------------
extern "C" void kernel_launch(void* const* d_in, const int* in_sizes, int n_in,
                              void* d_out, int out_size)
{
    const float* x   = (const float*)d_in[0];
    const float* Wq  = (const float*)d_in[1];
    const float* bq  = (const float*)d_in[2];
    const float* Wkv = (const float*)d_in[3];
    const float* bkv = (const float*)d_in[4];
    const float* Wo  = (const float*)d_in[5];
    float* out = (float*)d_out;

    __half *xs, *wq, *wkv, *wo, *as;
    cudaGetSymbolAddress((void**)&xs,  g_xs);
    cudaGetSymbolAddress((void**)&wq,  g_wq);
    cudaGetSymbolAddress((void**)&wkv, g_wkv);
    cudaGetSymbolAddress((void**)&wo,  g_wo);
    cudaGetSymbolAddress((void**)&as,  g_as);

    cudaFuncSetAttribute(gemm_qkv, cudaFuncAttributeMaxDynamicSharedMemorySize, QKV_SMEM);
    cudaFuncSetAttribute(gemm_fp16, cudaFuncAttributeMaxDynamicSharedMemorySize, GEMM_SMEM);
    cudaFuncSetAttribute(attn_mma, cudaFuncAttributeMaxDynamicSharedMemorySize, ATTN_SMEM);

    prep_kernel<<<(PREP_TOTAL + 255) / 256, 256>>>(x, Wq, Wkv, Wo);

    gemm_qkv<<<dim3(24, 32), dim3(256), QKV_SMEM>>>(xs, wq, wkv, bq, bkv);

    attn_mma<<<dim3(S_LEN / 64, NHEADS, NBATCH), dim3(128), ATTN_SMEM>>>();

    gemm_fp16<<<dim3(16, 32), dim3(256), GEMM_SMEM>>>(as, wo, out, EMB, EMB);
}

// round 15
// speedup vs baseline: 1.0417x; 1.0417x over previous
#include <cuda_runtime.h>
#include <cuda_fp16.h>
#include <math.h>
#include <stdint.h>

#define S_LEN   2048
#define NBATCH  2
#define EMB     2048
#define NHEADS  16
#define NKV     4
#define HD      128
#define KVW     1024   // 2*NKV*HD

// ---------------- scratch (device globals: no allocation allowed) ----------------
__device__ float  g_cs[S_LEN * 64];   // cos table [s][d]
__device__ float  g_sn[S_LEN * 64];   // sin table [s][d]
// fp16 operand buffers
__device__ __half g_xs [(size_t)NBATCH * S_LEN * EMB];     // x
__device__ __half g_wq [(size_t)EMB * EMB];
__device__ __half g_wkv[(size_t)KVW * EMB];
__device__ __half g_wo [(size_t)EMB * EMB];
__device__ __half g_qs [(size_t)NBATCH * S_LEN * EMB];     // rope Q (scale folded)
__device__ __half g_ks [(size_t)NBATCH * S_LEN * NKV * HD];
__device__ __half g_vs [(size_t)NBATCH * S_LEN * NKV * HD];
__device__ __half g_as [(size_t)NBATCH * S_LEN * EMB];     // attention out

// ---------------- fast exp --------------------------------------------------------
__device__ __forceinline__ float fast_exp(float x) {
    float y  = fmaxf(x * 1.4426950408889634f, -127.0f);
    float fl = floorf(y);
    float f  = y - fl;
    float p  = 1.5403530e-4f;
    p = fmaf(p, f, 1.3333558e-3f);
    p = fmaf(p, f, 9.6181291e-3f);
    p = fmaf(p, f, 5.5504109e-2f);
    p = fmaf(p, f, 2.4022651e-1f);
    p = fmaf(p, f, 6.9314718e-1f);
    p = fmaf(p, f, 1.0f);
    int e = (int)fl;
    float s = __int_as_float((e + 127) << 23);
    return p * s;
}

// ---------------- mma.sync / ldmatrix / cp.async helpers --------------------------
__device__ __forceinline__ uint32_t smem_u32(const void* p) {
    uint32_t a;
    asm("{ .reg .u64 t; cvta.to.shared.u64 t, %1; cvt.u32.u64 %0, t; }" : "=r"(a) : "l"(p));
    return a;
}
#define LDSM_X4(r0, r1, r2, r3, addr) \
    asm volatile("ldmatrix.sync.aligned.m8n8.x4.shared.b16 {%0,%1,%2,%3}, [%4];" \
        : "=r"(r0), "=r"(r1), "=r"(r2), "=r"(r3) : "r"(addr))
#define LDSM_T_X4(r0, r1, r2, r3, addr) \
    asm volatile("ldmatrix.sync.aligned.m8n8.x4.trans.shared.b16 {%0,%1,%2,%3}, [%4];" \
        : "=r"(r0), "=r"(r1), "=r"(r2), "=r"(r3) : "r"(addr))
#define MMAH(c0, c1, c2, c3, a0, a1, a2, a3, b0, b1) \
    asm volatile("mma.sync.aligned.m16n8k16.row.col.f32.f16.f16.f32 " \
        "{%0,%1,%2,%3}, {%4,%5,%6,%7}, {%8,%9}, {%0,%1,%2,%3};" \
        : "+f"(c0), "+f"(c1), "+f"(c2), "+f"(c3) \
        : "r"(a0), "r"(a1), "r"(a2), "r"(a3), "r"(b0), "r"(b1))
#define CP16(d, s) \
    asm volatile("cp.async.cg.shared.global [%0], [%1], 16;" :: "r"(d), "l"(s))
#define CP_COMMIT asm volatile("cp.async.commit_group;" ::: "memory")
#define CP_WAIT1  asm volatile("cp.async.wait_group 1;" ::: "memory")
#define CP_WAIT0  asm volatile("cp.async.wait_group 0;" ::: "memory")

// ================= merged prep: splits + rope tables (one launch) =================
#define NX4   (NBATCH * S_LEN * EMB / 4)
#define NWQ4  (EMB * EMB / 4)
#define NWKV4 (KVW * EMB / 4)
#define NTAB  (S_LEN * 64)
#define PREP_TOTAL (NX4 + NWQ4 + NWKV4 + NWQ4 + NTAB)

__global__ void prep_kernel(const float* __restrict__ x,  const float* __restrict__ Wq,
                            const float* __restrict__ Wkv, const float* __restrict__ Wo)
{
    int i = blockIdx.x * blockDim.x + threadIdx.x;
    const float* src;
    __half* dst;
    if (i < NX4)                      { src = x;   dst = g_xs; }
    else if ((i -= NX4) < NWQ4)       { src = Wq;  dst = g_wq; }
    else if ((i -= NWQ4) < NWKV4)     { src = Wkv; dst = g_wkv; }
    else if ((i -= NWKV4) < NWQ4)     { src = Wo;  dst = g_wo; }
    else {
        i -= NWQ4;
        if (i >= NTAB) return;
        int s = i >> 6, d = i & 63;
        double invf = pow(10000.0, -(double)d / 64.0);
        double ang = (double)s * invf;
        double k = floor(ang * 0.15915494309189535);
        float a = (float)(ang - k * 6.283185307179586);
        g_cs[i] = cosf(a);
        g_sn[i] = sinf(a);
        return;
    }
    float4 v = ((const float4*)src)[i];
    __half2 h01 = __floats2half2_rn(v.x, v.y);
    __half2 h23 = __floats2half2_rn(v.z, v.w);
    uint2 hv; hv.x = *(uint32_t*)&h01; hv.y = *(uint32_t*)&h23;
    ((uint2*)dst)[i] = hv;
}

// ===== GEMM mainloop: K-chunk 64, 3-stage ring, ONE sync/chunk, load-first ========
#define GS_ROW    72                       // padded row: 72 halfs = 144 B (9x16B, odd)
#define GS_TILE   (128 * GS_ROW * 2)       // 18432 B
#define GS_STAGE  (2 * GS_TILE)            // 36864 B (A, W)
#define GEMM_SMEM (3 * GS_STAGE)           // 110592 B
#define QKV_SMEM  GEMM_SMEM                // epilogue fp32 tile 67584 B fits

#define LOAD_STAGE(c, bufi) do {                                                       \
    int _k0 = (c) << 6;                                                                \
    uint32_t _st = sbase + (uint32_t)((bufi) * GS_STAGE);                              \
    _Pragma("unroll")                                                                  \
    for (int _i = 0; _i < 4; _i++) {                                                   \
        int _ch = tid + _i * 256;                                                      \
        int _r = _ch >> 3, _cl = _ch & 7;                                              \
        uint32_t _d = _st + (uint32_t)(_r * (GS_ROW * 2) + _cl * 16);                  \
        CP16(_d,           A_gp + (size_t)(m0 + _r) * Kd + _k0 + _cl * 8);             \
        CP16(_d + GS_TILE, W_gp + (size_t)(n0 + _r) * Kd + _k0 + _cl * 8);             \
    } } while (0)

#define GEMM_MAINLOOP(K)                                                               \
    const int rIT  = lane & 7;                                                         \
    const int b0_  = (lane >> 3) & 1;                                                  \
    const int b1_  = (lane >> 4) & 1;                                                  \
    const uint32_t aLane = (uint32_t)(((b0_ * 8 + rIT) * GS_ROW + b1_ * 8) * 2);       \
    const uint32_t bLane = (uint32_t)(((b1_ * 8 + rIT) * GS_ROW + b0_ * 8) * 2);       \
    const int nch = (K) >> 6;                                                          \
    LOAD_STAGE(0, 0); CP_COMMIT;                                                       \
    LOAD_STAGE(1, 1); CP_COMMIT;                                                       \
    int buf = 0;                                                                       \
    for (int c = 0; c < nch; c++) {                                                    \
        if (c + 1 < nch) CP_WAIT1; else CP_WAIT0;                                      \
        __syncthreads();                                                               \
        if (c + 2 < nch) {                                                             \
            int nb = buf + 2; if (nb >= 3) nb -= 3;                                    \
            LOAD_STAGE(c + 2, nb); CP_COMMIT;                                          \
        }                                                                              \
        const uint32_t bb = sbase + (uint32_t)(buf * GS_STAGE);                        \
        const uint32_t Ahs = bb;                                                       \
        const uint32_t Whs = bb + GS_TILE;                                             \
        _Pragma("unroll")                                                              \
        for (int ks = 0; ks < 4; ks++) {                                               \
            const uint32_t kOff = (uint32_t)(ks * 32);                                 \
            uint32_t ah[4][4], bh[4][2];                                               \
            _Pragma("unroll")                                                          \
            for (int mf = 0; mf < 4; mf++) {                                           \
                uint32_t addr = Ahs + (uint32_t)((wm + mf * 16) * GS_ROW * 2) + kOff + aLane; \
                LDSM_X4(ah[mf][0], ah[mf][1], ah[mf][2], ah[mf][3], addr);             \
            }                                                                          \
            _Pragma("unroll")                                                          \
            for (int np = 0; np < 2; np++) {                                           \
                uint32_t addr = Whs + (uint32_t)((wn + np * 16) * GS_ROW * 2) + kOff + bLane; \
                uint32_t r0, r1, r2, r3;                                               \
                LDSM_X4(r0, r1, r2, r3, addr);                                         \
                bh[np * 2][0] = r0; bh[np * 2][1] = r1;                                \
                bh[np * 2 + 1][0] = r2; bh[np * 2 + 1][1] = r3;                        \
            }                                                                          \
            _Pragma("unroll")                                                          \
            for (int mf = 0; mf < 4; mf++)                                             \
                _Pragma("unroll")                                                      \
                for (int nf = 0; nf < 4; nf++)                                         \
                    MMAH(acc[mf][nf][0], acc[mf][nf][1], acc[mf][nf][2], acc[mf][nf][3], \
                         ah[mf][0], ah[mf][1], ah[mf][2], ah[mf][3],                   \
                         bh[nf][0], bh[nf][1]);                                        \
        }                                                                              \
        if (++buf == 3) buf = 0;                                                       \
    }

// ================= fused QKV projection + RoPE/convert ============================
__global__ __launch_bounds__(256, 2)
void gemm_qkv(const __half* __restrict__ xs_g,
              const __half* __restrict__ wq_g, const __half* __restrict__ wkv_g,
              const float* __restrict__ bq_g, const float* __restrict__ bkv_g)
{
    extern __shared__ char smp[];
    const uint32_t sbase = smem_u32(smp);

    const int tid  = threadIdx.x;
    const int wid  = tid >> 5;
    const int lane = tid & 31;
    const int bx   = blockIdx.x;
    const bool isQ = bx < 16;
    const int m0   = blockIdx.y * 128;
    const int n0   = isQ ? bx * 128 : (bx - 16) * 128;
    const int wm   = (wid >> 2) * 64;
    const int wn   = (wid & 3) * 32;
    const int Kd   = EMB;

    const __half* A_gp = xs_g;
    const __half* W_gp = isQ ? wq_g : wkv_g;
    const float*  bias = isQ ? bq_g : bkv_g;

    float acc[4][4][4];
    #pragma unroll
    for (int i = 0; i < 4; i++)
        #pragma unroll
        for (int j = 0; j < 4; j++)
            #pragma unroll
            for (int e = 0; e < 4; e++) acc[i][j][e] = 0.f;

    GEMM_MAINLOOP(EMB)

    const int trow  = lane >> 2;
    const int tcol2 = (lane & 3) * 2;
    #pragma unroll
    for (int nf = 0; nf < 4; nf++) {
        float2 bv = *(const float2*)&bias[n0 + wn + nf * 8 + tcol2];
        #pragma unroll
        for (int mf = 0; mf < 4; mf++) {
            acc[mf][nf][0] += bv.x; acc[mf][nf][1] += bv.y;
            acc[mf][nf][2] += bv.x; acc[mf][nf][3] += bv.y;
        }
    }

    if (!isQ && n0 >= 512) {
        // ---- V tile: direct fp16 convert ----
        #pragma unroll
        for (int mf = 0; mf < 4; mf++) {
            #pragma unroll
            for (int nf = 0; nf < 4; nf++) {
                int grow = m0 + wm + mf * 16 + trow;
                int vcol = n0 - 512 + wn + nf * 8 + tcol2;
                __half2 ha = __floats2half2_rn(acc[mf][nf][0], acc[mf][nf][1]);
                __half2 hb = __floats2half2_rn(acc[mf][nf][2], acc[mf][nf][3]);
                *(uint32_t*)&g_vs[(size_t)grow * 512 + vcol]       = *(uint32_t*)&ha;
                *(uint32_t*)&g_vs[(size_t)(grow + 8) * 512 + vcol] = *(uint32_t*)&hb;
            }
        }
        return;
    }

    // ---- Q or K tile: stage fp32 to smem, RoPE, store fp16 ----
    __syncthreads();
    float* smf = (float*)smp;           // [128][132]
    #pragma unroll
    for (int mf = 0; mf < 4; mf++) {
        #pragma unroll
        for (int nf = 0; nf < 4; nf++) {
            int r = wm + mf * 16 + trow;
            int cidx = wn + nf * 8 + tcol2;
            *(float2*)&smf[r * 132 + cidx]       = make_float2(acc[mf][nf][0], acc[mf][nf][1]);
            *(float2*)&smf[(r + 8) * 132 + cidx] = make_float2(acc[mf][nf][2], acc[mf][nf][3]);
        }
    }
    __syncthreads();

    const float sc = isQ ? 0.08838834764831845f : 1.0f;
    __half* dst    = isQ ? g_qs : g_ks;
    const int width = isQ ? EMB : 512;

    #pragma unroll
    for (int i = 0; i < 16; i++) {
        int idx = tid + i * 256;
        int row = idx >> 5;
        int dp  = (idx & 31) * 2;
        int grow = m0 + row;
        int s = grow & (S_LEN - 1);
        float t1a = smf[row * 132 + dp];
        float t1b = smf[row * 132 + dp + 1];
        float t2a = smf[row * 132 + dp + 64];
        float t2b = smf[row * 132 + dp + 65];
        float2 csv = *(const float2*)&g_cs[s * 64 + dp];
        float2 snv = *(const float2*)&g_sn[s * 64 + dp];
        float o1a = (t1a * csv.x - t2a * snv.x) * sc;
        float o1b = (t1b * csv.y - t2b * snv.y) * sc;
        float o2a = (t2a * csv.x + t1a * snv.x) * sc;
        float o2b = (t2b * csv.y + t1b * snv.y) * sc;
        __half2 h1 = __floats2half2_rn(o1a, o1b);
        __half2 h2 = __floats2half2_rn(o2a, o2b);
        size_t ob = (size_t)grow * width + n0 + dp;
        *(uint32_t*)&dst[ob]      = *(uint32_t*)&h1;
        *(uint32_t*)&dst[ob + 64] = *(uint32_t*)&h2;
    }
}

// ================= plain GEMM for O projection ====================================
__global__ __launch_bounds__(256, 2)
void gemm_fp16(const __half* __restrict__ A_gp, const __half* __restrict__ W_gp,
               float* __restrict__ C, int N, int K)
{
    extern __shared__ char smp[];
    const uint32_t sbase = smem_u32(smp);

    const int tid  = threadIdx.x;
    const int wid  = tid >> 5;
    const int lane = tid & 31;
    const int m0   = blockIdx.y * 128;
    const int n0   = blockIdx.x * 128;
    const int wm   = (wid >> 2) * 64;
    const int wn   = (wid & 3) * 32;
    const int Kd   = K;

    float acc[4][4][4];
    #pragma unroll
    for (int i = 0; i < 4; i++)
        #pragma unroll
        for (int j = 0; j < 4; j++)
            #pragma unroll
            for (int e = 0; e < 4; e++) acc[i][j][e] = 0.f;

    GEMM_MAINLOOP(K)

    const int trow  = lane >> 2;
    const int tcol2 = (lane & 3) * 2;
    #pragma unroll
    for (int mf = 0; mf < 4; mf++) {
        #pragma unroll
        for (int nf = 0; nf < 4; nf++) {
            int row = m0 + wm + mf * 16 + trow;
            int col = n0 + wn + nf * 8 + tcol2;
            *(float2*)&C[(size_t)row * N + col]       = make_float2(acc[mf][nf][0], acc[mf][nf][1]);
            *(float2*)&C[(size_t)(row + 8) * N + col] = make_float2(acc[mf][nf][2], acc[mf][nf][3]);
        }
    }
}

// ===== fp16 HMMA attention (FA2, 64 rows, Q in regs, 2-buffer, occ 2) =============
#define AP        272
#define KT_BYTES  (64 * AP)
#define KVBUF     (2 * KT_BYTES)                 // K, V
#define ATTN_SMEM (2 * KVBUF)                    // 69632

__global__ __launch_bounds__(128, 2) void attn_mma() {
    extern __shared__ char smb[];
    const uint32_t sb = smem_u32(smb);

    const int tid  = threadIdx.x;
    const int wid  = tid >> 5;          // 0..3
    const int lane = tid & 31;
    const int q0   = blockIdx.x * 64;
    const int h    = blockIdx.y;
    const int b    = blockIdx.z;
    const int kvh  = h >> 2;

    const int rIT  = lane & 7;
    const int b3   = (lane >> 3) & 1;
    const int b4   = (lane >> 4) & 1;
    const uint32_t offA = (uint32_t)((b3 * 8 + rIT) * AP + b4 * 16);
    const uint32_t offB = (uint32_t)((b4 * 8 + rIT) * AP + b3 * 16);

    const __half* q_g = g_qs + (size_t)(b * S_LEN + q0) * EMB + h * HD;
    const __half* k_g = g_ks + (size_t)b * S_LEN * 512 + kvh * HD;
    const __half* v_g = g_vs + (size_t)b * S_LEN * 512 + kvh * HD;

    // ---- stage Q through buf0, LDSM to registers (loop-invariant) ----
    #pragma unroll
    for (int i = 0; i < 8; i++) {
        int c = tid + i * 128;
        int row = c >> 4, col = c & 15;
        CP16(sb + (uint32_t)(row * AP + col * 16), q_g + (size_t)row * EMB + col * 8);
    }
    CP_COMMIT; CP_WAIT0;
    __syncthreads();
    uint32_t qfr[8][4];
    {
        const uint32_t qwarp = sb + (uint32_t)(wid * 16 * AP);
        #pragma unroll
        for (int ks = 0; ks < 8; ks++)
            LDSM_X4(qfr[ks][0], qfr[ks][1], qfr[ks][2], qfr[ks][3], qwarp + ks * 32 + offA);
    }
    __syncthreads();

    #define LOAD_KV(T, BUF) do {                                                       \
        size_t _j = (size_t)((T) * 64);                                                \
        uint32_t _dst = sb + (uint32_t)((BUF) * KVBUF);                                \
        _Pragma("unroll")                                                              \
        for (int _i = 0; _i < 8; _i++) {                                               \
            int _c = tid + _i * 128;                                                   \
            int _row = _c >> 4, _col = _c & 15;                                        \
            uint32_t _d0 = _dst + (uint32_t)(_row * AP + _col * 16);                   \
            size_t _s0 = (_j + _row) * 512 + _col * 8;                                 \
            CP16(_d0,            k_g + _s0);                                           \
            CP16(_d0 + KT_BYTES, v_g + _s0);                                           \
        } } while (0)

    LOAD_KV(0, 0);
    CP_COMMIT;

    float m0 = -1e30f, m1 = -1e30f, l0 = 0.f, l1 = 0.f;
    float ofr[16][4];
    #pragma unroll
    for (int i = 0; i < 16; i++)
        #pragma unroll
        for (int e = 0; e < 4; e++) ofr[i][e] = 0.f;

    for (int t = 0; t < 32; t++) {
        if (t < 31) { LOAD_KV(t + 1, (t + 1) & 1); CP_COMMIT; CP_WAIT1; }
        else        { CP_WAIT0; }
        __syncthreads();

        const uint32_t kvb = sb + (uint32_t)((t & 1) * KVBUF);
        const uint32_t K_s = kvb;
        const uint32_t V_s = kvb + KT_BYTES;

        float sfr[8][4];
        #pragma unroll
        for (int i = 0; i < 8; i++)
            #pragma unroll
            for (int e = 0; e < 4; e++) sfr[i][e] = 0.f;

        #pragma unroll
        for (int ks = 0; ks < 8; ks++) {
            uint32_t bh[8][2];
            #pragma unroll
            for (int np = 0; np < 4; np++) {
                uint32_t r0, r1, r2, r3;
                LDSM_X4(r0, r1, r2, r3, K_s + (uint32_t)(np * 16 * AP) + ks * 32 + offB);
                bh[np * 2][0] = r0; bh[np * 2][1] = r1;
                bh[np * 2 + 1][0] = r2; bh[np * 2 + 1][1] = r3;
            }
            #pragma unroll
            for (int nf = 0; nf < 8; nf++)
                MMAH(sfr[nf][0], sfr[nf][1], sfr[nf][2], sfr[nf][3],
                     qfr[ks][0], qfr[ks][1], qfr[ks][2], qfr[ks][3],
                     bh[nf][0], bh[nf][1]);
        }

        float mx0 = -1e30f, mx1 = -1e30f;
        #pragma unroll
        for (int nf = 0; nf < 8; nf++) {
            mx0 = fmaxf(mx0, fmaxf(sfr[nf][0], sfr[nf][1]));
            mx1 = fmaxf(mx1, fmaxf(sfr[nf][2], sfr[nf][3]));
        }
        mx0 = fmaxf(mx0, __shfl_xor_sync(0xffffffffu, mx0, 1));
        mx0 = fmaxf(mx0, __shfl_xor_sync(0xffffffffu, mx0, 2));
        mx1 = fmaxf(mx1, __shfl_xor_sync(0xffffffffu, mx1, 1));
        mx1 = fmaxf(mx1, __shfl_xor_sync(0xffffffffu, mx1, 2));
        float mn0 = fmaxf(m0, mx0), mn1 = fmaxf(m1, mx1);
        float al0 = fast_exp(m0 - mn0), al1 = fast_exp(m1 - mn1);

        uint32_t ph[4][4];
        float rs0 = 0.f, rs1 = 0.f;
        #pragma unroll
        for (int nf = 0; nf < 8; nf++) {
            float p0 = fast_exp(sfr[nf][0] - mn0);
            float p1 = fast_exp(sfr[nf][1] - mn0);
            float p2 = fast_exp(sfr[nf][2] - mn1);
            float p3 = fast_exp(sfr[nf][3] - mn1);
            rs0 += p0 + p1; rs1 += p2 + p3;
            __half2 h01 = __floats2half2_rn(p0, p1);
            __half2 h23 = __floats2half2_rn(p2, p3);
            int kb = nf >> 1, hf = (nf & 1) * 2;
            ph[kb][hf]     = *(uint32_t*)&h01;
            ph[kb][hf + 1] = *(uint32_t*)&h23;
        }
        rs0 += __shfl_xor_sync(0xffffffffu, rs0, 1);
        rs0 += __shfl_xor_sync(0xffffffffu, rs0, 2);
        rs1 += __shfl_xor_sync(0xffffffffu, rs1, 1);
        rs1 += __shfl_xor_sync(0xffffffffu, rs1, 2);
        l0 = l0 * al0 + rs0;
        l1 = l1 * al1 + rs1;
        m0 = mn0; m1 = mn1;

        #pragma unroll
        for (int nf = 0; nf < 16; nf++) {
            ofr[nf][0] *= al0; ofr[nf][1] *= al0;
            ofr[nf][2] *= al1; ofr[nf][3] *= al1;
        }

        #pragma unroll
        for (int kb = 0; kb < 4; kb++) {
            #pragma unroll
            for (int db = 0; db < 8; db++) {
                uint32_t vh0, vh1, vh2, vh3;
                uint32_t va = (uint32_t)(kb * 16 * AP + db * 32) + offA;
                LDSM_T_X4(vh0, vh1, vh2, vh3, V_s + va);
                int nf = db * 2;
                MMAH(ofr[nf][0], ofr[nf][1], ofr[nf][2], ofr[nf][3],
                     ph[kb][0], ph[kb][1], ph[kb][2], ph[kb][3], vh0, vh1);
                MMAH(ofr[nf + 1][0], ofr[nf + 1][1], ofr[nf + 1][2], ofr[nf + 1][3],
                     ph[kb][0], ph[kb][1], ph[kb][2], ph[kb][3], vh2, vh3);
            }
        }
        __syncthreads();
    }

    float li0 = 1.0f / l0, li1 = 1.0f / l1;
    int row0 = q0 + wid * 16 + (lane >> 2);
    size_t ob = (size_t)(b * S_LEN + row0) * EMB + h * HD + (lane & 3) * 2;
    #pragma unroll
    for (int nf = 0; nf < 16; nf++) {
        __half2 h01 = __floats2half2_rn(ofr[nf][0] * li0, ofr[nf][1] * li0);
        __half2 h23 = __floats2half2_rn(ofr[nf][2] * li1, ofr[nf][3] * li1);
        *(uint32_t*)&g_as[ob + nf * 8]           = *(uint32_t*)&h01;
        *(uint32_t*)&g_as[ob + 8 * EMB + nf * 8] = *(uint32_t*)&h23;
    }
    #undef LOAD_KV
}

// ---------------- launch ----------------------------------------------------------
extern "C" void kernel_launch(void* const* d_in, const int* in_sizes, int n_in,
                              void* d_out, int out_size)
{
    const float* x   = (const float*)d_in[0];
    const float* Wq  = (const float*)d_in[1];
    const float* bq  = (const float*)d_in[2];
    const float* Wkv = (const float*)d_in[3];
    const float* bkv = (const float*)d_in[4];
    const float* Wo  = (const float*)d_in[5];
    float* out = (float*)d_out;

    __half *xs, *wq, *wkv, *wo, *as;
    cudaGetSymbolAddress((void**)&xs,  g_xs);
    cudaGetSymbolAddress((void**)&wq,  g_wq);
    cudaGetSymbolAddress((void**)&wkv, g_wkv);
    cudaGetSymbolAddress((void**)&wo,  g_wo);
    cudaGetSymbolAddress((void**)&as,  g_as);

    cudaFuncSetAttribute(gemm_qkv, cudaFuncAttributeMaxDynamicSharedMemorySize, QKV_SMEM);
    cudaFuncSetAttribute(gemm_fp16, cudaFuncAttributeMaxDynamicSharedMemorySize, GEMM_SMEM);
    cudaFuncSetAttribute(attn_mma, cudaFuncAttributeMaxDynamicSharedMemorySize, ATTN_SMEM);

    prep_kernel<<<(PREP_TOTAL + 255) / 256, 256>>>(x, Wq, Wkv, Wo);

    gemm_qkv<<<dim3(24, 32), dim3(256), QKV_SMEM>>>(xs, wq, wkv, bq, bkv);

    attn_mma<<<dim3(S_LEN / 64, NHEADS, NBATCH), dim3(128), ATTN_SMEM>>>();

    gemm_fp16<<<dim3(16, 32), dim3(256), GEMM_SMEM>>>(as, wo, out, EMB, EMB);
}